// round 1
// baseline (speedup 1.0000x reference)
#include <cuda_runtime.h>
#include <math.h>

// Problem constants
#define Bb 4
#define Ts 2048
#define Cc 1024
#define Hh 16
#define Dd 64

// Scratch (allocation-free: __device__ globals)
__device__ float g_q[Bb*Hh*Ts*Dd];   // [B,H,T,D]
__device__ float g_k[Bb*Hh*Ts*Dd];
__device__ float g_v[Bb*Hh*Ts*Dd];
__device__ float g_y[Bb*Ts*Cc];      // [B,T,C] attention output

// ---------------------------------------------------------------------------
// QKV GEMM: X[8192,1024] @ Wqkv[1024,3072] + b, scatter into q/k/v [B,H,T,D]
// 128x128 block tile, 8x8 per thread, BK=16
// ---------------------------------------------------------------------------
__global__ __launch_bounds__(256)
void qkv_gemm_kernel(const float* __restrict__ X,
                     const float* __restrict__ W,
                     const float* __restrict__ bias)
{
    const int K = Cc, N = 3 * Cc;
    __shared__ __align__(16) float As[16][132];  // transposed A tile, padded
    __shared__ __align__(16) float Bs[16][128];

    const int tid = threadIdx.x;
    const int ty = tid >> 4, tx = tid & 15;
    const int m0 = blockIdx.y * 128;
    const int n0 = blockIdx.x * 128;

    float acc[8][8];
    #pragma unroll
    for (int i = 0; i < 8; i++)
        #pragma unroll
        for (int j = 0; j < 8; j++) acc[i][j] = 0.f;

    const int arow = tid >> 2;            // 0..63
    const int acol = (tid & 3) << 2;      // 0,4,8,12
    const int brw  = tid >> 5;            // 0..7
    const int bcl  = (tid & 31) << 2;     // 0..124

    for (int k0 = 0; k0 < K; k0 += 16) {
        #pragma unroll
        for (int it = 0; it < 2; it++) {
            int r = arow + it * 64;
            float4 va = *(const float4*)(X + (size_t)(m0 + r) * K + k0 + acol);
            As[acol+0][r] = va.x;
            As[acol+1][r] = va.y;
            As[acol+2][r] = va.z;
            As[acol+3][r] = va.w;
        }
        #pragma unroll
        for (int it = 0; it < 2; it++) {
            int r = brw + it * 8;
            *(float4*)(&Bs[r][bcl]) =
                *(const float4*)(W + (size_t)(k0 + r) * N + n0 + bcl);
        }
        __syncthreads();
        #pragma unroll
        for (int kk = 0; kk < 16; kk++) {
            float ra[8], rb[8];
            *(float4*)(ra)     = *(const float4*)(&As[kk][ty*8]);
            *(float4*)(ra + 4) = *(const float4*)(&As[kk][ty*8 + 4]);
            *(float4*)(rb)     = *(const float4*)(&Bs[kk][tx*8]);
            *(float4*)(rb + 4) = *(const float4*)(&Bs[kk][tx*8 + 4]);
            #pragma unroll
            for (int i = 0; i < 8; i++)
                #pragma unroll
                for (int j = 0; j < 8; j++)
                    acc[i][j] = fmaf(ra[i], rb[j], acc[i][j]);
        }
        __syncthreads();
    }

    // Scatter epilogue into [B,H,T,D]
    #pragma unroll
    for (int i = 0; i < 8; i++) {
        int m = m0 + ty*8 + i;
        int b = m >> 11;            // m / 2048
        int t = m & (Ts - 1);
        #pragma unroll
        for (int j = 0; j < 8; j++) {
            int n = n0 + tx*8 + j;
            float val = acc[i][j] + bias[n];
            int which = n >> 10;          // 0=q 1=k 2=v
            int c = n & (Cc - 1);
            int h = c >> 6, d = c & 63;
            float* dst = (which == 0) ? g_q : (which == 1 ? g_k : g_v);
            dst[(((size_t)(b * Hh + h) << 11) + t) * Dd + d] = val;
        }
    }
}

// ---------------------------------------------------------------------------
// Flash attention: per block one (b,h) and a 64-row Q tile; stream 64-key
// tiles with online softmax. Smem: Qs/Ks transposed [d][r], Vs [s][d],
// Ps [s][r]. 256 threads, 4x4 micro-tile per thread.
// ---------------------------------------------------------------------------
__global__ __launch_bounds__(256)
void attn_kernel()
{
    extern __shared__ float sm[];
    float* Qs = sm;                 // [64][68]  Qs[d][r] (pre-scaled by 1/8)
    float* Ks = sm + 64*68;         // [64][68]  Ks[d][c]
    float* Vs = sm + 2*64*68;       // [64][68]  Vs[s][d]
    float* Ps = sm + 3*64*68;       // [64][68]  Ps[s][r]

    const int tid = threadIdx.x;
    const int ty = tid >> 4, tx = tid & 15;
    const int qt = blockIdx.x;      // Q tile index
    const int bh = blockIdx.y;      // b*H + h

    const float* Qg = g_q + (size_t)bh * Ts * Dd;
    const float* Kg = g_k + (size_t)bh * Ts * Dd;
    const float* Vg = g_v + (size_t)bh * Ts * Dd;

    // Load Q tile transposed, fold in 1/sqrt(D)=0.125
    #pragma unroll
    for (int it = 0; it < 4; it++) {
        int idx = tid + it * 256;
        int r  = idx >> 4;
        int d4 = (idx & 15) << 2;
        float4 v = *(const float4*)(Qg + (size_t)(qt*64 + r) * Dd + d4);
        Qs[(d4+0)*68 + r] = v.x * 0.125f;
        Qs[(d4+1)*68 + r] = v.y * 0.125f;
        Qs[(d4+2)*68 + r] = v.z * 0.125f;
        Qs[(d4+3)*68 + r] = v.w * 0.125f;
    }

    float m_i[4], l_i[4], acc[4][4];
    #pragma unroll
    for (int i = 0; i < 4; i++) {
        m_i[i] = -1e30f;
        l_i[i] = 0.f;
        #pragma unroll
        for (int j = 0; j < 4; j++) acc[i][j] = 0.f;
    }

    for (int kt = 0; kt <= qt; kt++) {
        __syncthreads();   // previous Ps/Vs reads done; Q visible on 1st iter
        #pragma unroll
        for (int it = 0; it < 4; it++) {
            int idx = tid + it * 256;
            int r  = idx >> 4;
            int d4 = (idx & 15) << 2;
            float4 kv = *(const float4*)(Kg + (size_t)(kt*64 + r) * Dd + d4);
            Ks[(d4+0)*68 + r] = kv.x;
            Ks[(d4+1)*68 + r] = kv.y;
            Ks[(d4+2)*68 + r] = kv.z;
            Ks[(d4+3)*68 + r] = kv.w;
            *(float4*)(&Vs[r*68 + d4]) =
                *(const float4*)(Vg + (size_t)(kt*64 + r) * Dd + d4);
        }
        __syncthreads();

        // S = Q @ K^T (scaled), 4x4 per thread
        float s[4][4];
        #pragma unroll
        for (int i = 0; i < 4; i++)
            #pragma unroll
            for (int j = 0; j < 4; j++) s[i][j] = 0.f;

        #pragma unroll 4
        for (int d = 0; d < 64; d++) {
            float rq[4], rk[4];
            *(float4*)rq = *(const float4*)(Qs + d*68 + ty*4);
            *(float4*)rk = *(const float4*)(Ks + d*68 + tx*4);
            #pragma unroll
            for (int i = 0; i < 4; i++)
                #pragma unroll
                for (int j = 0; j < 4; j++)
                    s[i][j] = fmaf(rq[i], rk[j], s[i][j]);
        }

        // Causal mask only on the diagonal tile
        if (kt == qt) {
            #pragma unroll
            for (int i = 0; i < 4; i++) {
                int r = ty*4 + i;
                #pragma unroll
                for (int j = 0; j < 4; j++) {
                    int c = tx*4 + j;
                    if (c > r) s[i][j] = -1e30f;
                }
            }
        }

        // Online softmax update; write P transposed to smem
        #pragma unroll
        for (int i = 0; i < 4; i++) {
            float mx = fmaxf(fmaxf(s[i][0], s[i][1]), fmaxf(s[i][2], s[i][3]));
            #pragma unroll
            for (int off = 8; off > 0; off >>= 1)
                mx = fmaxf(mx, __shfl_xor_sync(0xffffffffu, mx, off));
            float mnew = fmaxf(m_i[i], mx);
            float cf = __expf(m_i[i] - mnew);
            m_i[i] = mnew;
            float ps = 0.f;
            #pragma unroll
            for (int j = 0; j < 4; j++) {
                float p = __expf(s[i][j] - mnew);
                s[i][j] = p;
                ps += p;
            }
            #pragma unroll
            for (int off = 8; off > 0; off >>= 1)
                ps += __shfl_xor_sync(0xffffffffu, ps, off);
            l_i[i] = l_i[i] * cf + ps;
            #pragma unroll
            for (int j = 0; j < 4; j++) {
                acc[i][j] *= cf;
                Ps[(tx*4 + j)*68 + ty*4 + i] = s[i][j];
            }
        }
        __syncthreads();

        // O += P @ V
        #pragma unroll 4
        for (int s0 = 0; s0 < 64; s0++) {
            float rp[4], rv[4];
            *(float4*)rp = *(const float4*)(Ps + s0*68 + ty*4);
            *(float4*)rv = *(const float4*)(Vs + s0*68 + tx*4);
            #pragma unroll
            for (int i = 0; i < 4; i++)
                #pragma unroll
                for (int j = 0; j < 4; j++)
                    acc[i][j] = fmaf(rp[i], rv[j], acc[i][j]);
        }
    }

    // Normalize and store to g_y [B,T,C]
    int b = bh >> 4, h = bh & 15;
    #pragma unroll
    for (int i = 0; i < 4; i++) {
        float inv = 1.0f / l_i[i];
        int t = qt*64 + ty*4 + i;
        #pragma unroll
        for (int j = 0; j < 4; j++) {
            int d = tx*4 + j;
            g_y[(size_t)(b * Ts + t) * Cc + h * Dd + d] = acc[i][j] * inv;
        }
    }
}

// ---------------------------------------------------------------------------
// Output projection: Y[8192,1024] @ Wout[1024,1024] + b -> out
// ---------------------------------------------------------------------------
__global__ __launch_bounds__(256)
void proj_gemm_kernel(const float* __restrict__ W,
                      const float* __restrict__ bias,
                      float* __restrict__ out)
{
    const int K = Cc, N = Cc;
    __shared__ __align__(16) float As[16][132];
    __shared__ __align__(16) float Bs[16][128];

    const int tid = threadIdx.x;
    const int ty = tid >> 4, tx = tid & 15;
    const int m0 = blockIdx.y * 128;
    const int n0 = blockIdx.x * 128;

    float acc[8][8];
    #pragma unroll
    for (int i = 0; i < 8; i++)
        #pragma unroll
        for (int j = 0; j < 8; j++) acc[i][j] = 0.f;

    const int arow = tid >> 2;
    const int acol = (tid & 3) << 2;
    const int brw  = tid >> 5;
    const int bcl  = (tid & 31) << 2;

    for (int k0 = 0; k0 < K; k0 += 16) {
        #pragma unroll
        for (int it = 0; it < 2; it++) {
            int r = arow + it * 64;
            float4 va = *(const float4*)(g_y + (size_t)(m0 + r) * K + k0 + acol);
            As[acol+0][r] = va.x;
            As[acol+1][r] = va.y;
            As[acol+2][r] = va.z;
            As[acol+3][r] = va.w;
        }
        #pragma unroll
        for (int it = 0; it < 2; it++) {
            int r = brw + it * 8;
            *(float4*)(&Bs[r][bcl]) =
                *(const float4*)(W + (size_t)(k0 + r) * N + n0 + bcl);
        }
        __syncthreads();
        #pragma unroll
        for (int kk = 0; kk < 16; kk++) {
            float ra[8], rb[8];
            *(float4*)(ra)     = *(const float4*)(&As[kk][ty*8]);
            *(float4*)(ra + 4) = *(const float4*)(&As[kk][ty*8 + 4]);
            *(float4*)(rb)     = *(const float4*)(&Bs[kk][tx*8]);
            *(float4*)(rb + 4) = *(const float4*)(&Bs[kk][tx*8 + 4]);
            #pragma unroll
            for (int i = 0; i < 8; i++)
                #pragma unroll
                for (int j = 0; j < 8; j++)
                    acc[i][j] = fmaf(ra[i], rb[j], acc[i][j]);
        }
        __syncthreads();
    }

    #pragma unroll
    for (int i = 0; i < 8; i++) {
        int m = m0 + ty*8 + i;
        #pragma unroll
        for (int j = 0; j < 8; j++) {
            int n = n0 + tx*8 + j;
            out[(size_t)m * N + n] = acc[i][j] + bias[n];
        }
    }
}

// ---------------------------------------------------------------------------
extern "C" void kernel_launch(void* const* d_in, const int* in_sizes, int n_in,
                              void* d_out, int out_size)
{
    (void)in_sizes; (void)n_in; (void)out_size;
    const float* x     = (const float*)d_in[0];
    const float* w_qkv = (const float*)d_in[1];
    const float* b_qkv = (const float*)d_in[2];
    const float* w_out = (const float*)d_in[3];
    const float* b_out = (const float*)d_in[4];
    float* out = (float*)d_out;

    // 1) QKV projection + scatter to [B,H,T,D]
    qkv_gemm_kernel<<<dim3(3*Cc/128, (Bb*Ts)/128), 256>>>(x, w_qkv, b_qkv);

    // 2) Flash attention (69632 B dynamic smem)
    const int attn_smem = 4 * 64 * 68 * (int)sizeof(float);
    cudaFuncSetAttribute(attn_kernel,
                         cudaFuncAttributeMaxDynamicSharedMemorySize, attn_smem);
    attn_kernel<<<dim3(Ts/64, Bb*Hh), 256, attn_smem>>>();

    // 3) Output projection
    proj_gemm_kernel<<<dim3(Cc/128, (Bb*Ts)/128), 256>>>(w_out, b_out, out);
}